// round 3
// baseline (speedup 1.0000x reference)
#include <cuda_runtime.h>
#include <stdint.h>
#include <math.h>

// Problem dims (fixed by the dataset)
#define D_MODEL 2048
#define D_FF    8192
#define NTOK    8192            // B*S = 4*2048
#define NW      ((size_t)D_FF * D_MODEL)   // 16,777,216 elems per weight

// ---------------- scratch (device globals: allocation-free rule) -----------
__device__ int8_t g_w1q[D_FF * D_MODEL];       // 16 MB
__device__ int8_t g_w2q[D_MODEL * D_FF];       // 16 MB
__device__ int8_t g_xq [NTOK * D_MODEL];       // 16 MB
__device__ int8_t g_hq [NTOK * D_FF];          // 64 MB
__device__ float  g_h  [NTOK * D_FF];          // 256 MB (fp32: quant-rounding fidelity)
__device__ float  g_fx [NTOK];                 // per-token dequant factor, phase 1
__device__ float  g_fh [NTOK];                 // per-token dequant factor, phase 2
__device__ float  g_part[1024];
__device__ float  g_s1, g_s2;                  // weight absmean scales

// ---------------- reduction helpers ---------------------------------------
__device__ __forceinline__ float warpSum(float v) {
#pragma unroll
    for (int o = 16; o; o >>= 1) v += __shfl_xor_sync(0xFFFFFFFFu, v, o);
    return v;
}
__device__ __forceinline__ float warpMax(float v) {
#pragma unroll
    for (int o = 16; o; o >>= 1) v = fmaxf(v, __shfl_xor_sync(0xFFFFFFFFu, v, o));
    return v;
}
// 256-thread block reductions (8 warps). Leading sync protects reuse.
__device__ __forceinline__ float blockSum256(float v) {
    __shared__ float red[9];
    int warp = threadIdx.x >> 5, lane = threadIdx.x & 31;
    __syncthreads();
    v = warpSum(v);
    if (lane == 0) red[warp] = v;
    __syncthreads();
    if (warp == 0) {
        float t = (lane < 8) ? red[lane] : 0.f;
        t = warpSum(t);
        if (lane == 0) red[8] = t;
    }
    __syncthreads();
    return red[8];
}
__device__ __forceinline__ float blockMax256(float v) {
    __shared__ float redm[9];
    int warp = threadIdx.x >> 5, lane = threadIdx.x & 31;
    __syncthreads();
    v = warpMax(v);
    if (lane == 0) redm[warp] = v;
    __syncthreads();
    if (warp == 0) {
        float t = (lane < 8) ? redm[lane] : 0.f;   // values are >= 0
        t = warpMax(t);
        if (lane == 0) redm[8] = t;
    }
    __syncthreads();
    return redm[8];
}

// ---------------- weight absmean (two-pass, deterministic) -----------------
__global__ void k_abssum(const float* __restrict__ w, int n4) {
    float s = 0.f;
    const float4* w4 = (const float4*)w;
    for (int i = blockIdx.x * blockDim.x + threadIdx.x; i < n4;
         i += gridDim.x * blockDim.x) {
        float4 v = w4[i];
        s += fabsf(v.x) + fabsf(v.y) + fabsf(v.z) + fabsf(v.w);
    }
    s = warpSum(s);
    __shared__ float red[8];
    int warp = threadIdx.x >> 5, lane = threadIdx.x & 31;
    if (lane == 0) red[warp] = s;
    __syncthreads();
    if (threadIdx.x == 0) {
        float t = 0.f;
#pragma unroll
        for (int i = 0; i < 8; i++) t += red[i];
        g_part[blockIdx.x] = t;
    }
}

template <int PH>
__global__ void k_absmean_final(float invn) {
    float s = 0.f;
    for (int i = threadIdx.x; i < 1024; i += 256) s += g_part[i];
    s = blockSum256(s);
    if (threadIdx.x == 0) {
        float m = fmaxf(s * invn, 1e-8f);   // jnp.clip(mean|w|, 1e-8)
        if (PH == 1) g_s1 = m; else g_s2 = m;
    }
}

// ---------------- ternary weight quant -------------------------------------
template <int PH>
__global__ void k_quant_w(const float* __restrict__ w, int n4) {
    const float s = (PH == 1) ? g_s1 : g_s2;
    int8_t* q = (PH == 1) ? g_w1q : g_w2q;
    const float4* w4 = (const float4*)w;
    char4* q4 = (char4*)q;
    for (int i = blockIdx.x * blockDim.x + threadIdx.x; i < n4;
         i += gridDim.x * blockDim.x) {
        float4 v = w4[i];
        char4 c;
        c.x = (signed char)fminf(1.f, fmaxf(-1.f, rintf(v.x / s)));
        c.y = (signed char)fminf(1.f, fmaxf(-1.f, rintf(v.y / s)));
        c.z = (signed char)fminf(1.f, fmaxf(-1.f, rintf(v.z / s)));
        c.w = (signed char)fminf(1.f, fmaxf(-1.f, rintf(v.w / s)));
        q4[i] = c;
    }
}

// ---------------- fused LayerNorm + per-token absmax int8 quant ------------
// One 256-thread block per token row. PH=1: D=2048 from x. PH=2: D=8192 from g_h.
template <int PH>
__global__ void k_ln_quant(const float* __restrict__ xin) {
    constexpr int D = (PH == 1) ? D_MODEL : D_FF;
    constexpr int VPT = D / 256;   // 8 or 32
    const float* in = (PH == 1) ? xin : g_h;
    int8_t* qout = (PH == 1) ? g_xq : g_hq;
    float* fout = (PH == 1) ? g_fx : g_fh;

    const int row = blockIdx.x;
    const float4* src = (const float4*)(in + (size_t)row * D);

    float v[VPT];
#pragma unroll
    for (int k = 0; k < VPT / 4; k++) {
        float4 t = src[k * 256 + threadIdx.x];
        v[k * 4 + 0] = t.x; v[k * 4 + 1] = t.y;
        v[k * 4 + 2] = t.z; v[k * 4 + 3] = t.w;
    }
    float s = 0.f;
#pragma unroll
    for (int i = 0; i < VPT; i++) s += v[i];
    const float mu = blockSum256(s) * (1.f / (float)D);

    float sq = 0.f, am = 0.f;
#pragma unroll
    for (int i = 0; i < VPT; i++) {
        float c = v[i] - mu;
        v[i] = c;
        sq += c * c;
        am = fmaxf(am, fabsf(c));
    }
    const float var = blockSum256(sq) * (1.f / (float)D);
    const float rs = rsqrtf(var + 1e-5f);            // eps = 1e-5, biased var
    const float amax = blockMax256(am) * rs;          // absmax of normalized row
    const float qs = 127.f / fmaxf(amax, 1e-5f);      // jnp.clip(amax, 1e-5)

    char4* dst = (char4*)(qout + (size_t)row * D);
#pragma unroll
    for (int k = 0; k < VPT / 4; k++) {
        char4 c;
        int q0, q1, q2, q3;
        float xn;
        xn = v[k * 4 + 0] * rs; q0 = (int)rintf(xn * qs);
        xn = v[k * 4 + 1] * rs; q1 = (int)rintf(xn * qs);
        xn = v[k * 4 + 2] * rs; q2 = (int)rintf(xn * qs);
        xn = v[k * 4 + 3] * rs; q3 = (int)rintf(xn * qs);
        c.x = (signed char)max(-128, min(127, q0));
        c.y = (signed char)max(-128, min(127, q1));
        c.z = (signed char)max(-128, min(127, q2));
        c.w = (signed char)max(-128, min(127, q3));
        dst[k * 256 + threadIdx.x] = c;
    }
    if (threadIdx.x == 0) fout[row] = fmaxf(amax, 1e-5f) * (1.f / 127.f);
}

// ---------------- int8 GEMM via mma.sync.m16n8k32 --------------------------
__device__ __forceinline__ void mma_s8(int* d, const int* a, const int* b) {
    asm volatile(
        "mma.sync.aligned.m16n8k32.row.col.s32.s8.s8.s32 "
        "{%0,%1,%2,%3}, {%4,%5,%6,%7}, {%8,%9}, {%0,%1,%2,%3};\n"
        : "+r"(d[0]), "+r"(d[1]), "+r"(d[2]), "+r"(d[3])
        : "r"(a[0]), "r"(a[1]), "r"(a[2]), "r"(a[3]), "r"(b[0]), "r"(b[1]));
}

// C[M,N] = A[M,K] (s8, K-major) x B[N,K] (s8, K-major), exact int32 accum.
// Epilogue: dequant (per-row factor * scalar weight scale) + bias (+ exact GELU).
// BM=128, BN=128, BK=64. 8 warps: 4 (m) x 2 (n); warp tile 32x64.
template <int PH>
__launch_bounds__(256)
__global__ void k_gemm(const float* __restrict__ bias, float* __restrict__ outp) {
    constexpr int N = (PH == 1) ? D_FF : D_MODEL;
    constexpr int K = (PH == 1) ? D_MODEL : D_FF;
    const int8_t* A = (PH == 1) ? g_xq : g_hq;
    const int8_t* B = (PH == 1) ? g_w1q : g_w2q;
    const float* fa = (PH == 1) ? g_fx : g_fh;
    const float sw = (PH == 1) ? g_s1 : g_s2;
    float* out = (PH == 1) ? g_h : outp;

    // smem rows padded: 16 int32 data + 4 pad = stride 20 (conflict-free, 16B aligned)
    __shared__ int As[2][128 * 20];
    __shared__ int Bs[2][128 * 20];

    const int tid = threadIdx.x;
    const int warp = tid >> 5, lane = tid & 31;
    const int wm = warp & 3, wn = warp >> 2;
    const int group = lane >> 2, tig = lane & 3;
    const int bm = blockIdx.y * 128, bn = blockIdx.x * 128;

    int acc[2][8][4];
#pragma unroll
    for (int i = 0; i < 2; i++)
#pragma unroll
        for (int j = 0; j < 8; j++)
#pragma unroll
            for (int r = 0; r < 4; r++) acc[i][j][r] = 0;

    // each thread loads 2x16B from A and B per tile (rows tid>>2 and +64)
    const int r0 = tid >> 2, c0 = tid & 3;
    const int8_t* aptr = A + (size_t)(bm + r0) * K + c0 * 16;
    const int8_t* bptr = B + (size_t)(bn + r0) * K + c0 * 16;

    uint4 pa0, pa1, pb0, pb1;
    {
        pa0 = *(const uint4*)(aptr);
        pa1 = *(const uint4*)(aptr + (size_t)64 * K);
        pb0 = *(const uint4*)(bptr);
        pb1 = *(const uint4*)(bptr + (size_t)64 * K);
        *(uint4*)&As[0][r0 * 20 + c0 * 4] = pa0;
        *(uint4*)&As[0][(r0 + 64) * 20 + c0 * 4] = pa1;
        *(uint4*)&Bs[0][r0 * 20 + c0 * 4] = pb0;
        *(uint4*)&Bs[0][(r0 + 64) * 20 + c0 * 4] = pb1;
    }
    __syncthreads();

    constexpr int KT = K / 64;
    for (int kt = 0; kt < KT; kt++) {
        const int buf = kt & 1;
        if (kt + 1 < KT) {
            const size_t ko = (size_t)(kt + 1) * 64;
            pa0 = *(const uint4*)(aptr + ko);
            pa1 = *(const uint4*)(aptr + (size_t)64 * K + ko);
            pb0 = *(const uint4*)(bptr + ko);
            pb1 = *(const uint4*)(bptr + (size_t)64 * K + ko);
        }
#pragma unroll
        for (int ks = 0; ks < 2; ks++) {
            int a[2][4], b[8][2];
#pragma unroll
            for (int i = 0; i < 2; i++) {
                const int rr = wm * 32 + i * 16 + group;
                a[i][0] = As[buf][rr * 20 + ks * 8 + tig];
                a[i][1] = As[buf][(rr + 8) * 20 + ks * 8 + tig];
                a[i][2] = As[buf][rr * 20 + ks * 8 + tig + 4];
                a[i][3] = As[buf][(rr + 8) * 20 + ks * 8 + tig + 4];
            }
#pragma unroll
            for (int j = 0; j < 8; j++) {
                const int cc = wn * 64 + j * 8 + group;
                b[j][0] = Bs[buf][cc * 20 + ks * 8 + tig];
                b[j][1] = Bs[buf][cc * 20 + ks * 8 + tig + 4];
            }
#pragma unroll
            for (int i = 0; i < 2; i++)
#pragma unroll
                for (int j = 0; j < 8; j++) mma_s8(acc[i][j], a[i], b[j]);
        }
        if (kt + 1 < KT) {
            const int nb = buf ^ 1;
            *(uint4*)&As[nb][r0 * 20 + c0 * 4] = pa0;
            *(uint4*)&As[nb][(r0 + 64) * 20 + c0 * 4] = pa1;
            *(uint4*)&Bs[nb][r0 * 20 + c0 * 4] = pb0;
            *(uint4*)&Bs[nb][(r0 + 64) * 20 + c0 * 4] = pb1;
        }
        __syncthreads();
    }

    // epilogue: exact integer -> fp32 dequant, bias, (gelu), store
#pragma unroll
    for (int i = 0; i < 2; i++) {
#pragma unroll
        for (int half = 0; half < 2; half++) {
            const int row = bm + wm * 32 + i * 16 + group + half * 8;
            const float frow = fa[row] * sw;
#pragma unroll
            for (int j = 0; j < 8; j++) {
                const int col = bn + wn * 64 + j * 8 + tig * 2;
#pragma unroll
                for (int q = 0; q < 2; q++) {
                    float vv = (float)acc[i][j][half * 2 + q] * frow + bias[col + q];
                    if (PH == 1)
                        vv = 0.5f * vv * (1.f + erff(vv * 0.70710678118654752f));
                    out[(size_t)row * N + col + q] = vv;
                }
            }
        }
    }
}

// ---------------- launch ----------------------------------------------------
extern "C" void kernel_launch(void* const* d_in, const int* in_sizes, int n_in,
                              void* d_out, int out_size) {
    const float* x  = (const float*)d_in[0];
    const float* w1 = (const float*)d_in[1];
    const float* b1 = (const float*)d_in[2];
    const float* w2 = (const float*)d_in[3];
    const float* b2 = (const float*)d_in[4];
    float* out = (float*)d_out;

    const int n4 = (int)(NW / 4);
    const float invn = 1.f / (float)NW;

    // weight scales + ternary quant (w2 reuses g_part after w1 finishes; same stream)
    k_abssum<<<1024, 256>>>(w1, n4);
    k_absmean_final<1><<<1, 256>>>(invn);
    k_quant_w<1><<<1024, 256>>>(w1, n4);
    k_abssum<<<1024, 256>>>(w2, n4);
    k_absmean_final<2><<<1, 256>>>(invn);
    k_quant_w<2><<<1024, 256>>>(w2, n4);

    // LN + quant x
    k_ln_quant<1><<<NTOK, 256>>>(x);
    // GEMM1 + bias + exact GELU -> g_h (fp32)
    k_gemm<1><<<dim3(D_FF / 128, NTOK / 128), 256>>>(b1, nullptr);
    // LN + quant h
    k_ln_quant<2><<<NTOK, 256>>>(nullptr);
    // GEMM2 + bias -> output
    k_gemm<2><<<dim3(D_MODEL / 128, NTOK / 128), 256>>>(b2, out);
}